// round 15
// baseline (speedup 1.0000x reference)
#include <cuda_runtime.h>
#include <cstdint>
#include <cub/cub.cuh>

#define NN  16384
#define DD  256
#define KK  4096
#define BLK 128
#define NBT (NN / BLK)
#define CAP (1 << 18)
#define T_ADD 0.15f
#define T_RM  (-0.09f)

// ---- static device scratch ----
__device__ unsigned int        g_bitmap[(size_t)NN * NN / 32];
__device__ unsigned long long  g_add_keys[CAP];
__device__ unsigned long long  g_rm_keys[CAP];
__device__ unsigned long long  g_add_sorted[CAP];
__device__ unsigned long long  g_rm_sorted[CAP];
__device__ unsigned int        g_add_cnt;
__device__ unsigned int        g_rm_cnt;
__device__ float               g_nFr[NN], g_nSr[NN];   // R2 norms (rm side)
__device__ float               g_nFz[NN], g_nSz[NN];   // Z  norms (add side)
__device__ unsigned char       g_cub_tmp[32u << 20];

__device__ __forceinline__ unsigned int enc_f(float f) {
    unsigned int u = __float_as_uint(f);
    return (u & 0x80000000u) ? ~u : (u | 0x80000000u);
}
__device__ __forceinline__ float dec_f(unsigned int e) {
    unsigned int u = (e & 0x80000000u) ? (e ^ 0x80000000u) : ~e;
    return __uint_as_float(u);
}

// packed f32x2 helpers: lane0 = F chain, lane1 = S chain; each lane is an
// independent IEEE fma — bitwise identical to the scalar __fmaf_rn chains.
__device__ __forceinline__ unsigned long long pack2(float lo, float hi) {
    unsigned long long r;
    asm("mov.b64 %0, {%1, %2};" : "=l"(r) : "f"(lo), "f"(hi));
    return r;
}
__device__ __forceinline__ void unpack2(unsigned long long p, float& lo, float& hi) {
    asm("mov.b64 {%0, %1}, %2;" : "=f"(lo), "=f"(hi) : "l"(p));
}
__device__ __forceinline__ unsigned long long fma2(unsigned long long a,
                                                   unsigned long long b,
                                                   unsigned long long c) {
    unsigned long long r;
    asm("fma.rn.f32x2 %0, %1, %2, %3;" : "=l"(r) : "l"(a), "l"(b), "l"(c));
    return r;
}

__global__ void build_mask_kernel(const int* __restrict__ er,
                                  const int* __restrict__ ec, int E) {
    int t = blockIdx.x * blockDim.x + threadIdx.x;
    if (t < E) {
        unsigned pos = (unsigned)er[t] * NN + (unsigned)ec[t];
        atomicOr(&g_bitmap[pos >> 5], 1u << (pos & 31));
    } else if (t < E + NN) {
        unsigned i = (unsigned)(t - E);
        unsigned pos = i * NN + i;
        atomicOr(&g_bitmap[pos >> 5], 1u << (pos & 31));
    }
}

// ---- R2-norm VERBATIM (rm ordering verified EXACT). DO NOT TOUCH.
__global__ void norms_R2(const float* __restrict__ F, const float* __restrict__ S) {
    int warp = (blockIdx.x * blockDim.x + threadIdx.x) >> 5;
    int lane = threadIdx.x & 31;
    if (warp >= NN) return;
    const float4* f4 = (const float4*)(F + (size_t)warp * DD);
    const float4* s4 = (const float4*)(S + (size_t)warp * DD);
    float sf = 0.f, ss = 0.f;
    for (int i = lane; i < DD / 4; i += 32) {
        float4 a = f4[i];
        sf += a.x * a.x + a.y * a.y + a.z * a.z + a.w * a.w;
        float4 b = s4[i];
        ss += b.x * b.x + b.y * b.y + b.z * b.z + b.w * b.w;
    }
    #pragma unroll
    for (int o = 16; o > 0; o >>= 1) {
        sf += __shfl_xor_sync(0xFFFFFFFFu, sf, o);
        ss += __shfl_xor_sync(0xFFFFFFFFu, ss, o);
    }
    if (lane == 0) { g_nFr[warp] = sqrtf(sf); g_nSr[warp] = sqrtf(ss); }
}

__device__ __forceinline__ float leaf_halfsplit(float4 a) {
    return __fadd_rn(__fadd_rn(__fmul_rn(a.x, a.x), __fmul_rn(a.z, a.z)),
                     __fadd_rn(__fmul_rn(a.y, a.y), __fmul_rn(a.w, a.w)));
}

// ---- Z-norm VERBATIM (add ordering verified EXACT). DO NOT TOUCH.
__global__ void norms_Z(const float* __restrict__ F, const float* __restrict__ S) {
    int row = blockIdx.x;
    int t = threadIdx.x;            // 0..63
    int lane = t & 31, w = t >> 5;
    __shared__ float pF[2], pS[2];
    float sf = leaf_halfsplit(((const float4*)(F + (size_t)row * DD))[t]);
    float ss = leaf_halfsplit(((const float4*)(S + (size_t)row * DD))[t]);
    #pragma unroll
    for (int o = 16; o > 0; o >>= 1) {
        sf = __fadd_rn(sf, __shfl_down_sync(0xFFFFFFFFu, sf, o));
        ss = __fadd_rn(ss, __shfl_down_sync(0xFFFFFFFFu, ss, o));
    }
    if (lane == 0) { pF[w] = sf; pS[w] = ss; }
    __syncthreads();
    if (t == 0) {
        g_nFz[row] = sqrtf(__fadd_rn(pF[0], pF[1]));
        g_nSz[row] = sqrtf(__fadd_rn(pS[0], pS[1]));
    }
}

__device__ __forceinline__ void emit_rm(unsigned pos, float sim) {
    if (sim < T_RM) {
        unsigned bit = (g_bitmap[pos >> 5] >> (pos & 31)) & 1u;
        if (bit) {
            unsigned slot = atomicAdd(&g_rm_cnt, 1u);
            if (slot < CAP)
                g_rm_keys[slot] =
                    ((unsigned long long)enc_f(sim) << 32) | (unsigned long long)pos;
        }
    }
}
__device__ __forceinline__ void emit_add(unsigned pos, float sim) {
    if (sim > T_ADD) {
        unsigned bit = (g_bitmap[pos >> 5] >> (pos & 31)) & 1u;
        if (!bit) {
            unsigned slot = atomicAdd(&g_add_cnt, 1u);
            if (slot < CAP)
                g_add_keys[slot] =
                    ((unsigned long long)(~enc_f(sim)) << 32) | (unsigned long long)pos;
        }
    }
}

// ---- fused dual GEMM with packed FFMA2 mainloop.
// Each 64-bit accumulator = (accF in lane0, accS in lane1); fma.rn.f32x2
// applies an independent IEEE fma per lane, so each chain's rounding sequence
// is bitwise identical to the verified scalar FFMA chains (ascending k).
__global__ void __launch_bounds__(256, 1)
sim_fused(const float* __restrict__ F, const float* __restrict__ S) {
    __shared__ float AsF[16][BLK];
    __shared__ float AsS[16][BLK];
    __shared__ float BsF[16][BLK];
    __shared__ float BsS[16][BLK];

    int b = blockIdx.x;
    int ti = (int)(((float)(2 * NBT + 1) -
                    sqrtf((float)((2 * NBT + 1) * (2 * NBT + 1) - 8 * b))) * 0.5f);
    if (ti < 0) ti = 0;
    if (ti > NBT - 1) ti = NBT - 1;
    while (ti > 0 && ti * (2 * NBT - ti + 1) / 2 > b) ti--;
    while ((ti + 1) * (2 * NBT - ti) / 2 <= b) ti++;
    int tj = ti + (b - ti * (2 * NBT - ti + 1) / 2);

    int i0 = ti * BLK, j0 = tj * BLK;
    int tid = threadIdx.x;
    int tx = tid & 15, ty = tid >> 4;

    unsigned long long acc[8][8];
    #pragma unroll
    for (int u = 0; u < 8; u++)
        #pragma unroll
        for (int v = 0; v < 8; v++) acc[u][v] = 0ull;

    for (int k0 = 0; k0 < DD; k0 += 16) {
        __syncthreads();
        #pragma unroll
        for (int s = 0; s < 2; s++) {
            int slot = tid + s * 256;
            int r = slot >> 2;
            int kq = (slot & 3) * 4;
            float4 a = *(const float4*)(F + (size_t)(i0 + r) * DD + k0 + kq);
            AsF[kq + 0][r] = a.x; AsF[kq + 1][r] = a.y;
            AsF[kq + 2][r] = a.z; AsF[kq + 3][r] = a.w;
            float4 c = *(const float4*)(S + (size_t)(i0 + r) * DD + k0 + kq);
            AsS[kq + 0][r] = c.x; AsS[kq + 1][r] = c.y;
            AsS[kq + 2][r] = c.z; AsS[kq + 3][r] = c.w;
            float4 d = *(const float4*)(F + (size_t)(j0 + r) * DD + k0 + kq);
            BsF[kq + 0][r] = d.x; BsF[kq + 1][r] = d.y;
            BsF[kq + 2][r] = d.z; BsF[kq + 3][r] = d.w;
            float4 e = *(const float4*)(S + (size_t)(j0 + r) * DD + k0 + kq);
            BsS[kq + 0][r] = e.x; BsS[kq + 1][r] = e.y;
            BsS[kq + 2][r] = e.z; BsS[kq + 3][r] = e.w;
        }
        __syncthreads();

        #pragma unroll
        for (int k = 0; k < 16; k++) {
            unsigned long long aP[8], bP[8];
            {
                float4 t0 = *(const float4*)&AsF[k][ty * 8];
                float4 t1 = *(const float4*)&AsF[k][ty * 8 + 4];
                float4 s0 = *(const float4*)&AsS[k][ty * 8];
                float4 s1 = *(const float4*)&AsS[k][ty * 8 + 4];
                aP[0] = pack2(t0.x, s0.x); aP[1] = pack2(t0.y, s0.y);
                aP[2] = pack2(t0.z, s0.z); aP[3] = pack2(t0.w, s0.w);
                aP[4] = pack2(t1.x, s1.x); aP[5] = pack2(t1.y, s1.y);
                aP[6] = pack2(t1.z, s1.z); aP[7] = pack2(t1.w, s1.w);
            }
            {
                float4 t0 = *(const float4*)&BsF[k][tx * 8];
                float4 t1 = *(const float4*)&BsF[k][tx * 8 + 4];
                float4 s0 = *(const float4*)&BsS[k][tx * 8];
                float4 s1 = *(const float4*)&BsS[k][tx * 8 + 4];
                bP[0] = pack2(t0.x, s0.x); bP[1] = pack2(t0.y, s0.y);
                bP[2] = pack2(t0.z, s0.z); bP[3] = pack2(t0.w, s0.w);
                bP[4] = pack2(t1.x, s1.x); bP[5] = pack2(t1.y, s1.y);
                bP[6] = pack2(t1.z, s1.z); bP[7] = pack2(t1.w, s1.w);
            }
            #pragma unroll
            for (int u = 0; u < 8; u++)
                #pragma unroll
                for (int v = 0; v < 8; v++)
                    acc[u][v] = fma2(aP[u], bP[v], acc[u][v]);
        }
    }

    // epilogue: two sims per element, chains verbatim from the passing passes
    float rFi[8], rSi[8], rFj[8], rSj[8];   // R2 norms
    float zFi[8], zSi[8], zFj[8], zSj[8];   // Z norms
    #pragma unroll
    for (int u = 0; u < 8; u++) {
        rFi[u] = g_nFr[i0 + ty * 8 + u];  rSi[u] = g_nSr[i0 + ty * 8 + u];
        rFj[u] = g_nFr[j0 + tx * 8 + u];  rSj[u] = g_nSr[j0 + tx * 8 + u];
        zFi[u] = g_nFz[i0 + ty * 8 + u];  zSi[u] = g_nSz[i0 + ty * 8 + u];
        zFj[u] = g_nFz[j0 + tx * 8 + u];  zSj[u] = g_nSz[j0 + tx * 8 + u];
    }
    #pragma unroll
    for (int u = 0; u < 8; u++) {
        int gi = i0 + ty * 8 + u;
        #pragma unroll
        for (int v = 0; v < 8; v++) {
            int gj = j0 + tx * 8 + v;
            if (gi > gj) continue;
            unsigned pos  = (unsigned)gi * NN + (unsigned)gj;
            unsigned posT = (unsigned)gj * NN + (unsigned)gi;

            float accF, accS;
            unpack2(acc[u][v], accF, accS);

            float dFr = accF / fmaxf(rFi[u] * rFj[v], 1e-8f);
            float dSr = accS / fmaxf(rSi[u] * rSj[v], 1e-8f);
            float simR = 0.5f * dFr + 0.5f * dSr;
            emit_rm(pos, simR);
            if (gi < gj) emit_rm(posT, simR);

            float dFz = accF / fmaxf(zFi[u] * zFj[v], 1e-8f);
            float dSz = accS / fmaxf(zSi[u] * zSj[v], 1e-8f);
            float simZ = 0.5f * dFz + 0.5f * dSz;
            emit_add(pos, simZ);
            if (gi < gj) emit_add(posT, simZ);
        }
    }
}

__global__ void write_out_kernel(float* __restrict__ out, int out_size) {
    int t = blockIdx.x * blockDim.x + threadIdx.x;
    if (t >= KK) return;

    unsigned long long kr = g_rm_sorted[t];
    float rv = dec_f((unsigned)(kr >> 32));
    unsigned pr = (unsigned)kr;
    if (t < out_size) out[t] = rv;
    if (KK + 2 * t + 1 < out_size) {
        out[KK + 2 * t]     = (float)(pr / NN);
        out[KK + 2 * t + 1] = (float)(pr % NN);
    }

    unsigned long long ka = g_add_sorted[t];
    float av = dec_f(~(unsigned)(ka >> 32));
    unsigned pa = (unsigned)ka;
    if (3 * KK + t < out_size) out[3 * KK + t] = av;
    if (4 * KK + 2 * t + 1 < out_size) {
        out[4 * KK + 2 * t]     = (float)(pa / NN);
        out[4 * KK + 2 * t + 1] = (float)(pa % NN);
    }
}

extern "C" void kernel_launch(void* const* d_in, const int* in_sizes, int n_in,
                              void* d_out, int out_size) {
    const float* F  = (const float*)d_in[0];
    const float* S  = (const float*)d_in[1];
    const int*   er = (const int*)d_in[2];
    const int*   ec = (const int*)d_in[3];
    int E = in_sizes[2];

    void *p_bitmap, *p_addk, *p_rmk, *p_adds, *p_rms, *p_acnt, *p_rcnt, *p_tmp;
    cudaGetSymbolAddress(&p_bitmap, g_bitmap);
    cudaGetSymbolAddress(&p_addk,   g_add_keys);
    cudaGetSymbolAddress(&p_rmk,    g_rm_keys);
    cudaGetSymbolAddress(&p_adds,   g_add_sorted);
    cudaGetSymbolAddress(&p_rms,    g_rm_sorted);
    cudaGetSymbolAddress(&p_acnt,   g_add_cnt);
    cudaGetSymbolAddress(&p_rcnt,   g_rm_cnt);
    cudaGetSymbolAddress(&p_tmp,    g_cub_tmp);

    cudaMemsetAsync(p_bitmap, 0, (size_t)NN * NN / 8);
    cudaMemsetAsync(p_addk, 0xFF, (size_t)CAP * 8);
    cudaMemsetAsync(p_rmk,  0xFF, (size_t)CAP * 8);
    cudaMemsetAsync(p_acnt, 0, sizeof(unsigned int));
    cudaMemsetAsync(p_rcnt, 0, sizeof(unsigned int));

    build_mask_kernel<<<(E + NN + 255) / 256, 256>>>(er, ec, E);
    norms_R2<<<(NN * 32 + 255) / 256, 256>>>(F, S);
    norms_Z<<<NN, 64>>>(F, S);

    sim_fused<<<NBT * (NBT + 1) / 2, 256>>>(F, S);

    size_t tmp_bytes = 0;
    cub::DeviceRadixSort::SortKeys(nullptr, tmp_bytes,
                                   (const unsigned long long*)p_addk,
                                   (unsigned long long*)p_adds, CAP);
    if (tmp_bytes > (size_t)(32u << 20)) tmp_bytes = (size_t)(32u << 20);
    cub::DeviceRadixSort::SortKeys(p_tmp, tmp_bytes,
                                   (const unsigned long long*)p_rmk,
                                   (unsigned long long*)p_rms, CAP);
    cub::DeviceRadixSort::SortKeys(p_tmp, tmp_bytes,
                                   (const unsigned long long*)p_addk,
                                   (unsigned long long*)p_adds, CAP);

    write_out_kernel<<<(KK + 255) / 256, 256>>>((float*)d_out, out_size);
}

// round 17
// speedup vs baseline: 1.7136x; 1.7136x over previous
#include <cuda_runtime.h>
#include <cstdint>
#include <cub/cub.cuh>

#define NN  16384
#define DD  256
#define KK  4096
#define BLK 128
#define NBT (NN / BLK)
#define CAP (1 << 18)
#define T_ADD 0.15f
#define T_RM  (-0.09f)
#define QS   258          // padded q-stride in float4 units (16*16+2)

// ---- static device scratch ----
__device__ unsigned int        g_bitmap[(size_t)NN * NN / 32];
__device__ unsigned long long  g_add_keys[CAP];
__device__ unsigned long long  g_rm_keys[CAP];
__device__ unsigned long long  g_add_sorted[CAP];
__device__ unsigned long long  g_rm_sorted[CAP];
__device__ unsigned int        g_add_cnt;
__device__ unsigned int        g_rm_cnt;
__device__ float               g_nFr[NN], g_nSr[NN];   // R2 norms (rm side)
__device__ float               g_nFz[NN], g_nSz[NN];   // Z  norms (add side)
__device__ unsigned char       g_cub_tmp[32u << 20];

__device__ __forceinline__ unsigned int enc_f(float f) {
    unsigned int u = __float_as_uint(f);
    return (u & 0x80000000u) ? ~u : (u | 0x80000000u);
}
__device__ __forceinline__ float dec_f(unsigned int e) {
    unsigned int u = (e & 0x80000000u) ? (e ^ 0x80000000u) : ~e;
    return __uint_as_float(u);
}

__device__ __forceinline__ void unpack2(unsigned long long p, float& lo, float& hi) {
    asm("mov.b64 {%0, %1}, %2;" : "=f"(lo), "=f"(hi) : "l"(p));
}
// independent IEEE fma per 32-bit lane — bitwise identical to scalar chains
__device__ __forceinline__ unsigned long long fma2(unsigned long long a,
                                                   unsigned long long b,
                                                   unsigned long long c) {
    unsigned long long r;
    asm("fma.rn.f32x2 %0, %1, %2, %3;" : "=l"(r) : "l"(a), "l"(b), "l"(c));
    return r;
}

__global__ void build_mask_kernel(const int* __restrict__ er,
                                  const int* __restrict__ ec, int E) {
    int t = blockIdx.x * blockDim.x + threadIdx.x;
    if (t < E) {
        unsigned pos = (unsigned)er[t] * NN + (unsigned)ec[t];
        atomicOr(&g_bitmap[pos >> 5], 1u << (pos & 31));
    } else if (t < E + NN) {
        unsigned i = (unsigned)(t - E);
        unsigned pos = i * NN + i;
        atomicOr(&g_bitmap[pos >> 5], 1u << (pos & 31));
    }
}

// ---- R2-norm VERBATIM (rm ordering verified EXACT). DO NOT TOUCH.
__global__ void norms_R2(const float* __restrict__ F, const float* __restrict__ S) {
    int warp = (blockIdx.x * blockDim.x + threadIdx.x) >> 5;
    int lane = threadIdx.x & 31;
    if (warp >= NN) return;
    const float4* f4 = (const float4*)(F + (size_t)warp * DD);
    const float4* s4 = (const float4*)(S + (size_t)warp * DD);
    float sf = 0.f, ss = 0.f;
    for (int i = lane; i < DD / 4; i += 32) {
        float4 a = f4[i];
        sf += a.x * a.x + a.y * a.y + a.z * a.z + a.w * a.w;
        float4 b = s4[i];
        ss += b.x * b.x + b.y * b.y + b.z * b.z + b.w * b.w;
    }
    #pragma unroll
    for (int o = 16; o > 0; o >>= 1) {
        sf += __shfl_xor_sync(0xFFFFFFFFu, sf, o);
        ss += __shfl_xor_sync(0xFFFFFFFFu, ss, o);
    }
    if (lane == 0) { g_nFr[warp] = sqrtf(sf); g_nSr[warp] = sqrtf(ss); }
}

__device__ __forceinline__ float leaf_halfsplit(float4 a) {
    return __fadd_rn(__fadd_rn(__fmul_rn(a.x, a.x), __fmul_rn(a.z, a.z)),
                     __fadd_rn(__fmul_rn(a.y, a.y), __fmul_rn(a.w, a.w)));
}

// ---- Z-norm VERBATIM (add ordering verified EXACT). DO NOT TOUCH.
__global__ void norms_Z(const float* __restrict__ F, const float* __restrict__ S) {
    int row = blockIdx.x;
    int t = threadIdx.x;            // 0..63
    int lane = t & 31, w = t >> 5;
    __shared__ float pF[2], pS[2];
    float sf = leaf_halfsplit(((const float4*)(F + (size_t)row * DD))[t]);
    float ss = leaf_halfsplit(((const float4*)(S + (size_t)row * DD))[t]);
    #pragma unroll
    for (int o = 16; o > 0; o >>= 1) {
        sf = __fadd_rn(sf, __shfl_down_sync(0xFFFFFFFFu, sf, o));
        ss = __fadd_rn(ss, __shfl_down_sync(0xFFFFFFFFu, ss, o));
    }
    if (lane == 0) { pF[w] = sf; pS[w] = ss; }
    __syncthreads();
    if (t == 0) {
        g_nFz[row] = sqrtf(__fadd_rn(pF[0], pF[1]));
        g_nSz[row] = sqrtf(__fadd_rn(pS[0], pS[1]));
    }
}

__device__ __forceinline__ void emit_rm(unsigned pos, float sim) {
    if (sim < T_RM) {
        unsigned bit = (g_bitmap[pos >> 5] >> (pos & 31)) & 1u;
        if (bit) {
            unsigned slot = atomicAdd(&g_rm_cnt, 1u);
            if (slot < CAP)
                g_rm_keys[slot] =
                    ((unsigned long long)enc_f(sim) << 32) | (unsigned long long)pos;
        }
    }
}
__device__ __forceinline__ void emit_add(unsigned pos, float sim) {
    if (sim > T_ADD) {
        unsigned bit = (g_bitmap[pos >> 5] >> (pos & 31)) & 1u;
        if (!bit) {
            unsigned slot = atomicAdd(&g_add_cnt, 1u);
            if (slot < CAP)
                g_add_keys[slot] =
                    ((unsigned long long)(~enc_f(sim)) << 32) | (unsigned long long)pos;
        }
    }
}

// ---- fused dual GEMM: FFMA2 mainloop with smem-interleaved (F,S) pairs.
// smem float4 = {F[j],S[j],F[j+1],S[j+1]}: one LDS.128 = two packed operands,
// zero pack MOVs. Element j lives at (q=(j>>1)&3, t=j>>3, half=j&1).
// Each f32x2 lane runs the verified ascending-k IEEE fma chain — bitwise
// identical to the scalar version. Numerics frozen.
__global__ void __launch_bounds__(256, 1)
sim_fused(const float* __restrict__ F, const float* __restrict__ S) {
    __shared__ float4 As2[4 * QS];
    __shared__ float4 Bs2[4 * QS];

    int b = blockIdx.x;
    int ti = (int)(((float)(2 * NBT + 1) -
                    sqrtf((float)((2 * NBT + 1) * (2 * NBT + 1) - 8 * b))) * 0.5f);
    if (ti < 0) ti = 0;
    if (ti > NBT - 1) ti = NBT - 1;
    while (ti > 0 && ti * (2 * NBT - ti + 1) / 2 > b) ti--;
    while ((ti + 1) * (2 * NBT - ti) / 2 <= b) ti++;
    int tj = ti + (b - ti * (2 * NBT - ti + 1) / 2);

    int i0 = ti * BLK, j0 = tj * BLK;
    int tid = threadIdx.x;
    int tx = tid & 15, ty = tid >> 4;

    unsigned long long acc[8][8];
    #pragma unroll
    for (int u = 0; u < 8; u++)
        #pragma unroll
        for (int v = 0; v < 8; v++) acc[u][v] = 0ull;

    for (int k0 = 0; k0 < DD; k0 += 16) {
        __syncthreads();
        #pragma unroll
        for (int s = 0; s < 2; s++) {
            int slot = tid + s * 256;
            int r  = slot >> 2;               // row 0..127
            int kq = (slot & 3) * 4;          // k offset 0,4,8,12
            int q = (r >> 1) & 3, t = r >> 3, par = r & 1;
            float4 a = *(const float4*)(F + (size_t)(i0 + r) * DD + k0 + kq);
            float4 c = *(const float4*)(S + (size_t)(i0 + r) * DD + k0 + kq);
            ((float2*)&As2[q * QS + (kq + 0) * 16 + t])[par] = make_float2(a.x, c.x);
            ((float2*)&As2[q * QS + (kq + 1) * 16 + t])[par] = make_float2(a.y, c.y);
            ((float2*)&As2[q * QS + (kq + 2) * 16 + t])[par] = make_float2(a.z, c.z);
            ((float2*)&As2[q * QS + (kq + 3) * 16 + t])[par] = make_float2(a.w, c.w);
            float4 d = *(const float4*)(F + (size_t)(j0 + r) * DD + k0 + kq);
            float4 e = *(const float4*)(S + (size_t)(j0 + r) * DD + k0 + kq);
            ((float2*)&Bs2[q * QS + (kq + 0) * 16 + t])[par] = make_float2(d.x, e.x);
            ((float2*)&Bs2[q * QS + (kq + 1) * 16 + t])[par] = make_float2(d.y, e.y);
            ((float2*)&Bs2[q * QS + (kq + 2) * 16 + t])[par] = make_float2(d.z, e.z);
            ((float2*)&Bs2[q * QS + (kq + 3) * 16 + t])[par] = make_float2(d.w, e.w);
        }
        __syncthreads();

        #pragma unroll
        for (int k = 0; k < 16; k++) {
            unsigned long long aP[8], bP[8];
            #pragma unroll
            for (int q = 0; q < 4; q++) {
                ulonglong2 qa = *(const ulonglong2*)&As2[q * QS + k * 16 + ty];
                aP[2 * q]     = qa.x;
                aP[2 * q + 1] = qa.y;
                ulonglong2 qb = *(const ulonglong2*)&Bs2[q * QS + k * 16 + tx];
                bP[2 * q]     = qb.x;
                bP[2 * q + 1] = qb.y;
            }
            #pragma unroll
            for (int u = 0; u < 8; u++)
                #pragma unroll
                for (int v = 0; v < 8; v++)
                    acc[u][v] = fma2(aP[u], bP[v], acc[u][v]);
        }
    }

    // epilogue: two sims per element, chains verbatim from the passing passes
    float rFi[8], rSi[8], rFj[8], rSj[8];   // R2 norms
    float zFi[8], zSi[8], zFj[8], zSj[8];   // Z norms
    #pragma unroll
    for (int u = 0; u < 8; u++) {
        rFi[u] = g_nFr[i0 + ty * 8 + u];  rSi[u] = g_nSr[i0 + ty * 8 + u];
        rFj[u] = g_nFr[j0 + tx * 8 + u];  rSj[u] = g_nSr[j0 + tx * 8 + u];
        zFi[u] = g_nFz[i0 + ty * 8 + u];  zSi[u] = g_nSz[i0 + ty * 8 + u];
        zFj[u] = g_nFz[j0 + tx * 8 + u];  zSj[u] = g_nSz[j0 + tx * 8 + u];
    }
    #pragma unroll
    for (int u = 0; u < 8; u++) {
        int gi = i0 + ty * 8 + u;
        #pragma unroll
        for (int v = 0; v < 8; v++) {
            int gj = j0 + tx * 8 + v;
            if (gi > gj) continue;
            unsigned pos  = (unsigned)gi * NN + (unsigned)gj;
            unsigned posT = (unsigned)gj * NN + (unsigned)gi;

            float accF, accS;
            unpack2(acc[u][v], accF, accS);

            float dFr = accF / fmaxf(rFi[u] * rFj[v], 1e-8f);
            float dSr = accS / fmaxf(rSi[u] * rSj[v], 1e-8f);
            float simR = 0.5f * dFr + 0.5f * dSr;
            emit_rm(pos, simR);
            if (gi < gj) emit_rm(posT, simR);

            float dFz = accF / fmaxf(zFi[u] * zFj[v], 1e-8f);
            float dSz = accS / fmaxf(zSi[u] * zSj[v], 1e-8f);
            float simZ = 0.5f * dFz + 0.5f * dSz;
            emit_add(pos, simZ);
            if (gi < gj) emit_add(posT, simZ);
        }
    }
}

__global__ void write_out_kernel(float* __restrict__ out, int out_size) {
    int t = blockIdx.x * blockDim.x + threadIdx.x;
    if (t >= KK) return;

    unsigned long long kr = g_rm_sorted[t];
    float rv = dec_f((unsigned)(kr >> 32));
    unsigned pr = (unsigned)kr;
    if (t < out_size) out[t] = rv;
    if (KK + 2 * t + 1 < out_size) {
        out[KK + 2 * t]     = (float)(pr / NN);
        out[KK + 2 * t + 1] = (float)(pr % NN);
    }

    unsigned long long ka = g_add_sorted[t];
    float av = dec_f(~(unsigned)(ka >> 32));
    unsigned pa = (unsigned)ka;
    if (3 * KK + t < out_size) out[3 * KK + t] = av;
    if (4 * KK + 2 * t + 1 < out_size) {
        out[4 * KK + 2 * t]     = (float)(pa / NN);
        out[4 * KK + 2 * t + 1] = (float)(pa % NN);
    }
}

extern "C" void kernel_launch(void* const* d_in, const int* in_sizes, int n_in,
                              void* d_out, int out_size) {
    const float* F  = (const float*)d_in[0];
    const float* S  = (const float*)d_in[1];
    const int*   er = (const int*)d_in[2];
    const int*   ec = (const int*)d_in[3];
    int E = in_sizes[2];

    void *p_bitmap, *p_addk, *p_rmk, *p_adds, *p_rms, *p_acnt, *p_rcnt, *p_tmp;
    cudaGetSymbolAddress(&p_bitmap, g_bitmap);
    cudaGetSymbolAddress(&p_addk,   g_add_keys);
    cudaGetSymbolAddress(&p_rmk,    g_rm_keys);
    cudaGetSymbolAddress(&p_adds,   g_add_sorted);
    cudaGetSymbolAddress(&p_rms,    g_rm_sorted);
    cudaGetSymbolAddress(&p_acnt,   g_add_cnt);
    cudaGetSymbolAddress(&p_rcnt,   g_rm_cnt);
    cudaGetSymbolAddress(&p_tmp,    g_cub_tmp);

    cudaMemsetAsync(p_bitmap, 0, (size_t)NN * NN / 8);
    cudaMemsetAsync(p_addk, 0xFF, (size_t)CAP * 8);
    cudaMemsetAsync(p_rmk,  0xFF, (size_t)CAP * 8);
    cudaMemsetAsync(p_acnt, 0, sizeof(unsigned int));
    cudaMemsetAsync(p_rcnt, 0, sizeof(unsigned int));

    build_mask_kernel<<<(E + NN + 255) / 256, 256>>>(er, ec, E);
    norms_R2<<<(NN * 32 + 255) / 256, 256>>>(F, S);
    norms_Z<<<NN, 64>>>(F, S);

    sim_fused<<<NBT * (NBT + 1) / 2, 256>>>(F, S);

    size_t tmp_bytes = 0;
    cub::DeviceRadixSort::SortKeys(nullptr, tmp_bytes,
                                   (const unsigned long long*)p_addk,
                                   (unsigned long long*)p_adds, CAP);
    if (tmp_bytes > (size_t)(32u << 20)) tmp_bytes = (size_t)(32u << 20);
    cub::DeviceRadixSort::SortKeys(p_tmp, tmp_bytes,
                                   (const unsigned long long*)p_rmk,
                                   (unsigned long long*)p_rms, CAP);
    cub::DeviceRadixSort::SortKeys(p_tmp, tmp_bytes,
                                   (const unsigned long long*)p_addk,
                                   (unsigned long long*)p_adds, CAP);

    write_out_kernel<<<(KK + 255) / 256, 256>>>((float*)d_out, out_size);
}